// round 15
// baseline (speedup 1.0000x reference)
#include <cuda_runtime.h>
#include <math.h>

// GraphQNN: 22-qubit real-amplitude state-vector simulation.
// R15: exact R13 structure (3 sweeps, 512thr x 32elem, best measured 47.9us)
// with __launch_bounds__(512,3) on all sweeps: regs capped at 42 -> 3 CTAs/SM
// (192KB smem <= 228KB), 48 warps/SM instead of 32. Zero instruction-stream
// change (unlike R14's failed reshape) - pure occupancy knob.
//   S1 k_passIH: analytic init (combined L0+L1 angles) -> sign1 -> L2 hi
//   S2 k_passLL: L2 low -> sign2 -> L3 low
//   S3 k_passHE: L3 hi -> fused expvals

#define NQ 22
#define DIM (1 << NQ)
#define LOWB 14
#define LOWDIM (1 << LOWB)
#define FULL 0xffffffffu
typedef unsigned long long ull;

__device__ float g_state[DIM];
__device__ float g_ccs[4][NQ];     // staging, written by k_setup
__device__ float g_sss[4][NQ];
__device__ unsigned g_pms[NQ];

__constant__ float c_c[4][NQ];     // [stage][bitpos]; stage 0 = combined L0+L1
__constant__ float c_s[4][NQ];
__constant__ unsigned c_pm[NQ];

__device__ __forceinline__ unsigned par(unsigned v) {
    return (unsigned)__popc(v) & 1u;
}

// ---------------------------------------------------------------- f32x2
__device__ __forceinline__ ull pk2(float x, float y) {
    ull r; asm("mov.b64 %0, {%1,%2};" : "=l"(r) : "f"(x), "f"(y)); return r;
}
__device__ __forceinline__ float2 upk2(ull v) {
    float2 f; asm("mov.b64 {%0,%1}, %2;" : "=f"(f.x), "=f"(f.y) : "l"(v)); return f;
}
__device__ __forceinline__ ull mul2_(ull a, ull b) {
    ull r; asm("mul.rn.f32x2 %0, %1, %2;" : "=l"(r) : "l"(a), "l"(b)); return r;
}
__device__ __forceinline__ ull fma2_(ull a, ull b, ull c) {
    ull r; asm("fma.rn.f32x2 %0, %1, %2, %3;" : "=l"(r) : "l"(a), "l"(b), "l"(c)); return r;
}

// butterfly on 32 elements held as 16 pairs p[i] = (elem lo, elem hi).
// BIT = 0: pair-internal (scalar). BIT>=1: packed across pair-index bit BIT-1.
template <int BIT>
__device__ __forceinline__ void bflyp(ull* p, float c, float s) {
    if (BIT == 0) {
#pragma unroll
        for (int i = 0; i < 16; i++) {
            float2 v = upk2(p[i]);
            p[i] = pk2(fmaf(c, v.x, -(s * v.y)), fmaf(s, v.x, c * v.y));
        }
    } else {
        const ull cc = pk2(c, c), ss = pk2(s, s), ns = pk2(-s, -s);
#pragma unroll
        for (int i0 = 0; i0 < 16; i0++) {
            if ((i0 & (1 << (BIT - 1))) == 0) {
                int i1 = i0 | (1 << (BIT - 1));
                ull v0 = p[i0], v1 = p[i1];
                p[i0] = fma2_(cc, v0, mul2_(ns, v1));
                p[i1] = fma2_(ss, v0, mul2_(cc, v1));
            }
        }
    }
}

// ---------------------------------------------------------------- setup
__global__ void k_setup(const float* __restrict__ feat,
                        const float* __restrict__ adj,
                        const float* __restrict__ params,
                        float* __restrict__ out) {
    int t = threadIdx.x;
    if (t < 4 * NQ) {
        int s = t / NQ;
        int b = t % NQ;
        int q = NQ - 1 - b;
        float th;
        if (s == 0)       th = (feat[q] + params[q]) * 0.5f;   // combined L0+L1
        else              th = params[(s - 1) * NQ + q] * 0.5f;
        g_ccs[s][b] = cosf(th);
        g_sss[s][b] = sinf(th);
    }
    if (t < NQ) {
        int q = NQ - 1 - t;
        unsigned m = 0;
        for (int qq = 0; qq < NQ; qq++) {
            if (qq == q) continue;
            int i = q < qq ? q : qq;
            int j = q < qq ? qq : q;
            if (adj[i * NQ + j] > 0.0f) m |= (1u << (NQ - 1 - qq));
        }
        g_pms[t] = m;
        out[t] = 0.0f;
    }
}

__device__ __forceinline__ unsigned signB(unsigned ulow) {
    unsigned Bb = 0;
#pragma unroll
    for (int a = 1; a < LOWB; a++)
        Bb ^= ((ulow >> a) & 1u) & par(ulow & c_pm[a] & ((1u << a) - 1u));
    return Bb;
}
__device__ __forceinline__ unsigned signCL(unsigned ulow) {
    unsigned cl = 0;
#pragma unroll
    for (int j = 0; j < 8; j++)
        cl |= par(ulow & c_pm[14 + j] & 0x3FFFu) << j;
    return cl;
}

// ---------------------------------------------------------------- S1 passIH
// Analytic post-L1 product state -> sign1 -> stage S hi RYs -> store.
// View A: x = ((hv<<5)|k)<<14 | low; k = global 14-18 (pair = bit 14),
// hv = global 19-21.
template <int S>
__global__ void __launch_bounds__(512, 3) k_passIH() {
    extern __shared__ float sm[];
    const int t = threadIdx.x;
    const int lane = t & 31;
    const int tl = t & 63;
    const unsigned hv = t >> 6;          // global 19-21
    const int low = (blockIdx.x << 6) + tl;
    const unsigned ulow = (unsigned)low;

    // ---- sign constants (VIEW A)
    unsigned Bb = signB(ulow);
    unsigned cl = signCL(ulow);
    unsigned chm = 0;
#pragma unroll
    for (int a = 0; a < 5; a++)
        chm |= par(hv & ((c_pm[14 + a] >> 19) & 7u)) << a;
    unsigned Ahh = 0;
#pragma unroll
    for (int a = 1; a < 3; a++)
        Ahh ^= ((hv >> a) & 1u) & par(hv & ((c_pm[19 + a] >> 19) & ((1u << a) - 1u)));
    unsigned ab = 0;
#pragma unroll
    for (int a = 1; a < 5; a++)
        ab ^= (((unsigned)lane >> a) & 1u) &
              par((unsigned)lane & ((c_pm[14 + a] >> 14) & ((1u << a) - 1u)));
    const unsigned akk = __ballot_sync(FULL, ab);
    const unsigned km = (cl & 31u) ^ chm;
    const unsigned cbase = Bb ^ par(hv & (cl >> 5)) ^ Ahh;

    // ---- analytic product state (combined angles, stage 0)
    float a = 1.0f;
#pragma unroll
    for (int b = 0; b < LOWB; b++)
        a *= ((ulow >> b) & 1u) ? c_s[0][b] : c_c[0][b];
#pragma unroll
    for (int b = 0; b < 3; b++)
        a *= ((hv >> b) & 1u) ? c_s[0][19 + b] : c_c[0][19 + b];

    ull p[16];
#pragma unroll
    for (int i = 0; i < 16; i++) {
        float ai = a;
#pragma unroll
        for (int b = 0; b < 4; b++)               // k bits 1-4 = global 15-18
            ai *= ((i >> b) & 1) ? c_s[0][15 + b] : c_c[0][15 + b];
        float vlo = ai * c_c[0][14];              // k bit 0 (global 14) = 0
        float vhi = ai * c_s[0][14];              // k bit 0 = 1
        unsigned lo = cbase ^ ((akk >> (2 * i)) & 1u) ^ par((unsigned)(2 * i) & km);
        unsigned hi = cbase ^ ((akk >> (2 * i + 1)) & 1u) ^ par((unsigned)(2 * i + 1) & km);
        p[i] = pk2(__int_as_float(__float_as_int(vlo) ^ (lo << 31)),
                   __int_as_float(__float_as_int(vhi) ^ (hi << 31)));
    }

    // stage S global bits 14-18
    bflyp<0>(p, c_c[S][14], c_s[S][14]);
    bflyp<1>(p, c_c[S][15], c_s[S][15]);
    bflyp<2>(p, c_c[S][16], c_s[S][16]);
    bflyp<3>(p, c_c[S][17], c_s[S][17]);
    bflyp<4>(p, c_c[S][18], c_s[S][18]);

    // exchange A -> B (scalar, [h][tl], conflict-free)
#pragma unroll
    for (int i = 0; i < 16; i++) {
        float2 v = upk2(p[i]);
        sm[(((hv << 5) | (2 * i)) << 6) | tl] = v.x;
        sm[(((hv << 5) | (2 * i + 1)) << 6) | tl] = v.y;
    }
    __syncthreads();
#pragma unroll
    for (int i = 0; i < 16; i++)
        p[i] = pk2(sm[((((2 * i) << 3) | hv) << 6) | tl],
                   sm[((((2 * i + 1) << 3) | hv) << 6) | tl]);

    // stage S global bits 19-21 (view B k bits 2-4)
    bflyp<2>(p, c_c[S][19], c_s[S][19]);
    bflyp<3>(p, c_c[S][20], c_s[S][20]);
    bflyp<4>(p, c_c[S][21], c_s[S][21]);

    // store from view B: h = (k<<3)|hv
#pragma unroll
    for (int i = 0; i < 16; i++) {
        float2 v = upk2(p[i]);
        g_state[((((2 * i) << 3) | hv) << LOWB) | low] = v.x;
        g_state[((((2 * i + 1) << 3) | hv) << LOWB) | low] = v.y;
    }
}

// ---------------------------------------------------------------- S3 passHE
// stage S hi RYs + fused expvals.
template <int S>
__global__ void __launch_bounds__(512, 3) k_passHE(float* __restrict__ out) {
    extern __shared__ float sm[];
    __shared__ float acc[NQ];
    const int t = threadIdx.x;
    const int lane = t & 31;
    const int tl = t & 63;
    const unsigned hv = t >> 6;
    const int low = (blockIdx.x << 6) + tl;

    if (t < NQ) acc[t] = 0.0f;

    ull p[16];
#pragma unroll
    for (int i = 0; i < 16; i++)
        p[i] = pk2(g_state[(((hv << 5) | (2 * i)) << LOWB) | low],
                   g_state[(((hv << 5) | (2 * i + 1)) << LOWB) | low]);

    bflyp<0>(p, c_c[S][14], c_s[S][14]);
    bflyp<1>(p, c_c[S][15], c_s[S][15]);
    bflyp<2>(p, c_c[S][16], c_s[S][16]);
    bflyp<3>(p, c_c[S][17], c_s[S][17]);
    bflyp<4>(p, c_c[S][18], c_s[S][18]);

#pragma unroll
    for (int i = 0; i < 16; i++) {
        float2 v = upk2(p[i]);
        sm[(((hv << 5) | (2 * i)) << 6) | tl] = v.x;
        sm[(((hv << 5) | (2 * i + 1)) << 6) | tl] = v.y;
    }
    __syncthreads();
#pragma unroll
    for (int i = 0; i < 16; i++)
        p[i] = pk2(sm[((((2 * i) << 3) | hv) << 6) | tl],
                   sm[((((2 * i + 1) << 3) | hv) << 6) | tl]);

    bflyp<2>(p, c_c[S][19], c_s[S][19]);
    bflyp<3>(p, c_c[S][20], c_s[S][20]);
    bflyp<4>(p, c_c[S][21], c_s[S][21]);

    // expvals, view B element bits: 0-5 = tl, 6-13 = blk, 14-16 = hv,
    // 17 = pair, 18-21 = i.
    float P = 0.f, S17 = 0.f, S18 = 0.f, S19 = 0.f, S20 = 0.f, S21 = 0.f;
#pragma unroll
    for (int i = 0; i < 16; i++) {
        float2 v = upk2(p[i]);
        float px = v.x * v.x, py = v.y * v.y;
        float pp = px + py;
        P += pp;
        S17 += px - py;
        S18 += (i & 1) ? -pp : pp;
        S19 += (i & 2) ? -pp : pp;
        S20 += (i & 4) ? -pp : pp;
        S21 += (i & 8) ? -pp : pp;
    }
    float R0 = (lane & 1)  ? -P : P;
    float R1 = (lane & 2)  ? -P : P;
    float R2 = (lane & 4)  ? -P : P;
    float R3 = (lane & 8)  ? -P : P;
    float R4 = (lane & 16) ? -P : P;
#pragma unroll
    for (int o = 16; o; o >>= 1) {
        P   += __shfl_xor_sync(FULL, P, o);
        S17 += __shfl_xor_sync(FULL, S17, o);
        S18 += __shfl_xor_sync(FULL, S18, o);
        S19 += __shfl_xor_sync(FULL, S19, o);
        S20 += __shfl_xor_sync(FULL, S20, o);
        S21 += __shfl_xor_sync(FULL, S21, o);
        R0  += __shfl_xor_sync(FULL, R0, o);
        R1  += __shfl_xor_sync(FULL, R1, o);
        R2  += __shfl_xor_sync(FULL, R2, o);
        R3  += __shfl_xor_sync(FULL, R3, o);
        R4  += __shfl_xor_sync(FULL, R4, o);
    }
    if (lane == 0) {
        unsigned w = (unsigned)(t >> 5);
        atomicAdd(&acc[0], R0);
        atomicAdd(&acc[1], R1);
        atomicAdd(&acc[2], R2);
        atomicAdd(&acc[3], R3);
        atomicAdd(&acc[4], R4);
        atomicAdd(&acc[5], (w & 1u) ? -P : P);
#pragma unroll
        for (int b = 6; b < 14; b++)
            atomicAdd(&acc[b], ((blockIdx.x >> (b - 6)) & 1) ? -P : P);
#pragma unroll
        for (int b = 14; b < 17; b++)
            atomicAdd(&acc[b], ((w >> (b - 13)) & 1u) ? -P : P);
        atomicAdd(&acc[17], S17);
        atomicAdd(&acc[18], S18);
        atomicAdd(&acc[19], S19);
        atomicAdd(&acc[20], S20);
        atomicAdd(&acc[21], S21);
    }
    __syncthreads();
    if (t < NQ) atomicAdd(&out[NQ - 1 - t], acc[t]);
}

// ---------------------------------------------------------------- L views
// Natural layout, pairs along x0. Swizzle keeps bit0: lw(x)=x^(((x>>5)&15)<<1).
__device__ __forceinline__ int lw(int x) { return x ^ (((x >> 5) & 15) << 1); }

// ---------------------------------------------------------------- S2 passLL
// SA = L2 bits 0-13 -> sign2 -> SB = L3 bits 0-13.
template <int SA, int SB>
__global__ void __launch_bounds__(512, 3) k_passLL() {
    extern __shared__ float sm[];   // 16384 floats
    const int t = threadIdx.x;           // 9 bits
    const int lane = t & 31;
    const int base = blockIdx.x << LOWB;
    const unsigned blk = blockIdx.x;
    ull p[16];

    // ---- load: natural ulonglong2, pairs along x0
    {
        const ulonglong2* gp =
            reinterpret_cast<const ulonglong2*>(&g_state[base + t * 32]);
#pragma unroll
        for (int j = 0; j < 8; j++) {
            ulonglong2 q = gp[j];
            p[2 * j] = q.x;
            p[2 * j + 1] = q.y;
        }
    }

    // ---- sign constants for the C view: x = blk<<14 | i<<10 | e<<9 | T9
    const int yc = ((t >> 4) & 1) | ((t & 15) << 1) | (((t >> 5) & 15) << 5);
    const unsigned T9 = (unsigned)yc;
    unsigned Mblk = 0;
#pragma unroll
    for (int j = 0; j < 8; j++)
        Mblk ^= (0u - ((blk >> j) & 1u)) & (c_pm[14 + j] & 0x3FFFu);
    unsigned Ablk = 0;
#pragma unroll
    for (int a = 1; a < 8; a++)
        Ablk ^= ((blk >> a) & 1u) & par(blk & ((c_pm[14 + a] >> 14) & ((1u << a) - 1u)));
    unsigned Bt = 0;
#pragma unroll
    for (int a = 1; a < 9; a++)
        Bt ^= ((T9 >> a) & 1u) & par(T9 & c_pm[a] & ((1u << a) - 1u));
    const unsigned base_t = Bt ^ par(T9 & Mblk & 0x1FFu) ^ Ablk;
    const unsigned X9c = par(T9 & c_pm[9] & 0x1FFu) ^ ((Mblk >> 9) & 1u);
    unsigned km = 0;
#pragma unroll
    for (int b = 0; b < 4; b++)
        km |= (par(T9 & c_pm[10 + b] & 0x1FFu) ^ ((Mblk >> (10 + b)) & 1u)) << b;
    const unsigned mask9i = (c_pm[9] >> 10) & 15u;
    unsigned ab = 0;
#pragma unroll
    for (int a = 1; a < 4; a++)
        ab ^= (((unsigned)lane >> a) & 1u) &
              par((unsigned)lane & ((c_pm[10 + a] >> 10) & ((1u << a) - 1u)));
    const unsigned Wakk = __ballot_sync(FULL, ab);

    // ---- A: SA bits 0-4 (x0 internal, x1-4 packed)
    bflyp<0>(p, c_c[SA][0], c_s[SA][0]);
    bflyp<1>(p, c_c[SA][1], c_s[SA][1]);
    bflyp<2>(p, c_c[SA][2], c_s[SA][2]);
    bflyp<3>(p, c_c[SA][3], c_s[SA][3]);
    bflyp<4>(p, c_c[SA][4], c_s[SA][4]);

#pragma unroll
    for (int i = 0; i < 16; i++)
        *reinterpret_cast<ull*>(&sm[lw((t << 5) | (2 * i))]) = p[i];
    __syncthreads();

    // ---- B: SA bits 5-8
    const int yb = ((t & 15) << 1) | ((t >> 4) << 9);
#pragma unroll
    for (int i = 0; i < 16; i++)
        p[i] = *reinterpret_cast<const ull*>(&sm[lw(yb | (i << 5))]);

    bflyp<1>(p, c_c[SA][5], c_s[SA][5]);
    bflyp<2>(p, c_c[SA][6], c_s[SA][6]);
    bflyp<3>(p, c_c[SA][7], c_s[SA][7]);
    bflyp<4>(p, c_c[SA][8], c_s[SA][8]);

#pragma unroll
    for (int i = 0; i < 16; i++)
        *reinterpret_cast<ull*>(&sm[lw(yb | (i << 5))]) = p[i];
    __syncthreads();

    // ---- C: SA bits 9-13 -> SIGN -> SB bits 9-13
#pragma unroll
    for (int i = 0; i < 16; i++)
        p[i] = pk2(sm[lw(yc | ((2 * i) << 9))],
                   sm[lw(yc | ((2 * i + 1) << 9))]);

    bflyp<0>(p, c_c[SA][9],  c_s[SA][9]);
    bflyp<1>(p, c_c[SA][10], c_s[SA][10]);
    bflyp<2>(p, c_c[SA][11], c_s[SA][11]);
    bflyp<3>(p, c_c[SA][12], c_s[SA][12]);
    bflyp<4>(p, c_c[SA][13], c_s[SA][13]);

#pragma unroll
    for (int i = 0; i < 16; i++) {
        unsigned lo = base_t ^ par((unsigned)i & km) ^ ((Wakk >> i) & 1u);
        unsigned hi = lo ^ X9c ^ par((unsigned)i & mask9i);
        p[i] ^= ((ull)hi << 63) | ((ull)lo << 31);
    }

    bflyp<0>(p, c_c[SB][9],  c_s[SB][9]);
    bflyp<1>(p, c_c[SB][10], c_s[SB][10]);
    bflyp<2>(p, c_c[SB][11], c_s[SB][11]);
    bflyp<3>(p, c_c[SB][12], c_s[SB][12]);
    bflyp<4>(p, c_c[SB][13], c_s[SB][13]);

#pragma unroll
    for (int i = 0; i < 16; i++) {
        float2 v = upk2(p[i]);
        sm[lw(yc | ((2 * i) << 9))] = v.x;
        sm[lw(yc | ((2 * i + 1) << 9))] = v.y;
    }
    __syncthreads();

    // ---- B': SB bits 5-8
#pragma unroll
    for (int i = 0; i < 16; i++)
        p[i] = *reinterpret_cast<const ull*>(&sm[lw(yb | (i << 5))]);

    bflyp<1>(p, c_c[SB][5], c_s[SB][5]);
    bflyp<2>(p, c_c[SB][6], c_s[SB][6]);
    bflyp<3>(p, c_c[SB][7], c_s[SB][7]);
    bflyp<4>(p, c_c[SB][8], c_s[SB][8]);

#pragma unroll
    for (int i = 0; i < 16; i++)
        *reinterpret_cast<ull*>(&sm[lw(yb | (i << 5))]) = p[i];
    __syncthreads();

    // ---- A': SB bits 0-4, then natural ulonglong2 store
#pragma unroll
    for (int i = 0; i < 16; i++)
        p[i] = *reinterpret_cast<const ull*>(&sm[lw((t << 5) | (2 * i))]);

    bflyp<0>(p, c_c[SB][0], c_s[SB][0]);
    bflyp<1>(p, c_c[SB][1], c_s[SB][1]);
    bflyp<2>(p, c_c[SB][2], c_s[SB][2]);
    bflyp<3>(p, c_c[SB][3], c_s[SB][3]);
    bflyp<4>(p, c_c[SB][4], c_s[SB][4]);

    {
        ulonglong2* gp = reinterpret_cast<ulonglong2*>(&g_state[base + t * 32]);
#pragma unroll
        for (int j = 0; j < 8; j++) {
            ulonglong2 q;
            q.x = p[2 * j];
            q.y = p[2 * j + 1];
            gp[j] = q;
        }
    }
}

// ---------------------------------------------------------------- launch
extern "C" void kernel_launch(void* const* d_in, const int* in_sizes, int n_in,
                              void* d_out, int out_size) {
    const float* feat = (const float*)d_in[0];
    const float* adj = (const float*)d_in[1];
    const float* params = (const float*)d_in[2];
    float* out = (float*)d_out;

    const int SMEM = LOWDIM * (int)sizeof(float);   // 65536
    cudaFuncSetAttribute(k_passIH<2>,    cudaFuncAttributeMaxDynamicSharedMemorySize, SMEM);
    cudaFuncSetAttribute(k_passLL<2, 3>, cudaFuncAttributeMaxDynamicSharedMemorySize, SMEM);
    cudaFuncSetAttribute(k_passHE<3>,    cudaFuncAttributeMaxDynamicSharedMemorySize, SMEM);

    k_setup<<<1, 128>>>(feat, adj, params, out);

    // stage coefficients into __constant__ (D2D, graph-capturable)
    void *pc = nullptr, *ps = nullptr, *pm = nullptr;
    cudaGetSymbolAddress(&pc, g_ccs);
    cudaGetSymbolAddress(&ps, g_sss);
    cudaGetSymbolAddress(&pm, g_pms);
    cudaMemcpyToSymbolAsync(c_c, pc, sizeof(float) * 4 * NQ, 0, cudaMemcpyDeviceToDevice);
    cudaMemcpyToSymbolAsync(c_s, ps, sizeof(float) * 4 * NQ, 0, cudaMemcpyDeviceToDevice);
    cudaMemcpyToSymbolAsync(c_pm, pm, sizeof(unsigned) * NQ, 0, cudaMemcpyDeviceToDevice);

    k_passIH<2>   <<<LOWDIM / 64, 512, SMEM>>>();
    k_passLL<2, 3><<<DIM / LOWDIM, 512, SMEM>>>();
    k_passHE<3>   <<<LOWDIM / 64, 512, SMEM>>>(out);
}

// round 16
// speedup vs baseline: 1.1173x; 1.1173x over previous
#include <cuda_runtime.h>
#include <math.h>

// GraphQNN: 22-qubit real-amplitude state-vector simulation.
// R16: exact R13 structure (3 sweeps, 512thr x 32elem, best measured 47.9us)
// with LIFTING-SCHEME butterflies: R(th) = shear(-t) . shear(+s) . shear(-t),
// t = tan(th/2) = s/(1+c)  ->  3 FMAs per butterfly instead of 2 FMA + 2 MUL.
// ~25% fewer butterfly instructions in all three sweeps; t precomputed in
// __constant__. Launch config identical to R13 (2 CTAs/SM; R14/R15 occupancy
// experiments both regressed and are reverted).
//   S1 k_passIH: analytic init (combined L0+L1 angles) -> sign1 -> L2 hi
//   S2 k_passLL: L2 low -> sign2 -> L3 low
//   S3 k_passHE: L3 hi -> fused expvals

#define NQ 22
#define DIM (1 << NQ)
#define LOWB 14
#define LOWDIM (1 << LOWB)
#define FULL 0xffffffffu
typedef unsigned long long ull;

__device__ float g_state[DIM];
__device__ float g_ccs[4][NQ];     // staging, written by k_setup
__device__ float g_sss[4][NQ];
__device__ float g_tts[4][NQ];
__device__ unsigned g_pms[NQ];

__constant__ float c_c[4][NQ];     // cos(th/2)   [stage][bitpos]; stage0 = L0+L1
__constant__ float c_s[4][NQ];     // sin(th/2)
__constant__ float c_t[4][NQ];     // tan(th/4)-style lifting coef s/(1+c)
__constant__ unsigned c_pm[NQ];

__device__ __forceinline__ unsigned par(unsigned v) {
    return (unsigned)__popc(v) & 1u;
}

// ---------------------------------------------------------------- f32x2
__device__ __forceinline__ ull pk2(float x, float y) {
    ull r; asm("mov.b64 %0, {%1,%2};" : "=l"(r) : "f"(x), "f"(y)); return r;
}
__device__ __forceinline__ float2 upk2(ull v) {
    float2 f; asm("mov.b64 {%0,%1}, %2;" : "=f"(f.x), "=f"(f.y) : "l"(v)); return f;
}
__device__ __forceinline__ ull fma2_(ull a, ull b, ull c) {
    ull r; asm("fma.rn.f32x2 %0, %1, %2, %3;" : "=l"(r) : "l"(a), "l"(b), "l"(c)); return r;
}

// Lifting butterfly on 32 elements held as 16 pairs p[i] = (lo, hi).
// (x,y) -> (c x - s y, s x + c y) via x-=t*y; y+=s*x; x-=t*y.
// BIT = 0: pair-internal (scalar). BIT>=1: packed across pair-index bit BIT-1.
template <int BIT>
__device__ __forceinline__ void bflyp(ull* p, float s, float t) {
    if (BIT == 0) {
        const float nt = -t;
#pragma unroll
        for (int i = 0; i < 16; i++) {
            float2 v = upk2(p[i]);
            v.x = fmaf(nt, v.y, v.x);
            v.y = fmaf(s, v.x, v.y);
            v.x = fmaf(nt, v.y, v.x);
            p[i] = pk2(v.x, v.y);
        }
    } else {
        const ull nt = pk2(-t, -t), ss = pk2(s, s);
#pragma unroll
        for (int i0 = 0; i0 < 16; i0++) {
            if ((i0 & (1 << (BIT - 1))) == 0) {
                int i1 = i0 | (1 << (BIT - 1));
                ull v0 = p[i0], v1 = p[i1];
                v0 = fma2_(nt, v1, v0);
                v1 = fma2_(ss, v0, v1);
                v0 = fma2_(nt, v1, v0);
                p[i0] = v0;
                p[i1] = v1;
            }
        }
    }
}

#define BF(P, BIT, S, b) bflyp<BIT>(P, c_s[S][b], c_t[S][b])

// ---------------------------------------------------------------- setup
__global__ void k_setup(const float* __restrict__ feat,
                        const float* __restrict__ adj,
                        const float* __restrict__ params,
                        float* __restrict__ out) {
    int t = threadIdx.x;
    if (t < 4 * NQ) {
        int s = t / NQ;
        int b = t % NQ;
        int q = NQ - 1 - b;
        float th;
        if (s == 0)       th = (feat[q] + params[q]) * 0.5f;   // combined L0+L1
        else              th = params[(s - 1) * NQ + q] * 0.5f;
        float c = cosf(th), sn = sinf(th);
        g_ccs[s][b] = c;
        g_sss[s][b] = sn;
        g_tts[s][b] = sn / (1.0f + c);
    }
    if (t < NQ) {
        int q = NQ - 1 - t;
        unsigned m = 0;
        for (int qq = 0; qq < NQ; qq++) {
            if (qq == q) continue;
            int i = q < qq ? q : qq;
            int j = q < qq ? qq : q;
            if (adj[i * NQ + j] > 0.0f) m |= (1u << (NQ - 1 - qq));
        }
        g_pms[t] = m;
        out[t] = 0.0f;
    }
}

__device__ __forceinline__ unsigned signB(unsigned ulow) {
    unsigned Bb = 0;
#pragma unroll
    for (int a = 1; a < LOWB; a++)
        Bb ^= ((ulow >> a) & 1u) & par(ulow & c_pm[a] & ((1u << a) - 1u));
    return Bb;
}
__device__ __forceinline__ unsigned signCL(unsigned ulow) {
    unsigned cl = 0;
#pragma unroll
    for (int j = 0; j < 8; j++)
        cl |= par(ulow & c_pm[14 + j] & 0x3FFFu) << j;
    return cl;
}

// ---------------------------------------------------------------- S1 passIH
// Analytic post-L1 product state -> sign1 -> stage S hi RYs -> store.
// View A: x = ((hv<<5)|k)<<14 | low; k = global 14-18 (pair = bit 14),
// hv = global 19-21.
template <int S>
__global__ void __launch_bounds__(512, 2) k_passIH() {
    extern __shared__ float sm[];
    const int t = threadIdx.x;
    const int lane = t & 31;
    const int tl = t & 63;
    const unsigned hv = t >> 6;          // global 19-21
    const int low = (blockIdx.x << 6) + tl;
    const unsigned ulow = (unsigned)low;

    // ---- sign constants (VIEW A)
    unsigned Bb = signB(ulow);
    unsigned cl = signCL(ulow);
    unsigned chm = 0;
#pragma unroll
    for (int a = 0; a < 5; a++)
        chm |= par(hv & ((c_pm[14 + a] >> 19) & 7u)) << a;
    unsigned Ahh = 0;
#pragma unroll
    for (int a = 1; a < 3; a++)
        Ahh ^= ((hv >> a) & 1u) & par(hv & ((c_pm[19 + a] >> 19) & ((1u << a) - 1u)));
    unsigned ab = 0;
#pragma unroll
    for (int a = 1; a < 5; a++)
        ab ^= (((unsigned)lane >> a) & 1u) &
              par((unsigned)lane & ((c_pm[14 + a] >> 14) & ((1u << a) - 1u)));
    const unsigned akk = __ballot_sync(FULL, ab);
    const unsigned km = (cl & 31u) ^ chm;
    const unsigned cbase = Bb ^ par(hv & (cl >> 5)) ^ Ahh;

    // ---- analytic product state (combined angles, stage 0)
    float a = 1.0f;
#pragma unroll
    for (int b = 0; b < LOWB; b++)
        a *= ((ulow >> b) & 1u) ? c_s[0][b] : c_c[0][b];
#pragma unroll
    for (int b = 0; b < 3; b++)
        a *= ((hv >> b) & 1u) ? c_s[0][19 + b] : c_c[0][19 + b];

    ull p[16];
#pragma unroll
    for (int i = 0; i < 16; i++) {
        float ai = a;
#pragma unroll
        for (int b = 0; b < 4; b++)               // k bits 1-4 = global 15-18
            ai *= ((i >> b) & 1) ? c_s[0][15 + b] : c_c[0][15 + b];
        float vlo = ai * c_c[0][14];              // k bit 0 (global 14) = 0
        float vhi = ai * c_s[0][14];              // k bit 0 = 1
        unsigned lo = cbase ^ ((akk >> (2 * i)) & 1u) ^ par((unsigned)(2 * i) & km);
        unsigned hi = cbase ^ ((akk >> (2 * i + 1)) & 1u) ^ par((unsigned)(2 * i + 1) & km);
        p[i] = pk2(__int_as_float(__float_as_int(vlo) ^ (lo << 31)),
                   __int_as_float(__float_as_int(vhi) ^ (hi << 31)));
    }

    // stage S global bits 14-18
    BF(p, 0, S, 14);
    BF(p, 1, S, 15);
    BF(p, 2, S, 16);
    BF(p, 3, S, 17);
    BF(p, 4, S, 18);

    // exchange A -> B (scalar, [h][tl], conflict-free)
#pragma unroll
    for (int i = 0; i < 16; i++) {
        float2 v = upk2(p[i]);
        sm[(((hv << 5) | (2 * i)) << 6) | tl] = v.x;
        sm[(((hv << 5) | (2 * i + 1)) << 6) | tl] = v.y;
    }
    __syncthreads();
#pragma unroll
    for (int i = 0; i < 16; i++)
        p[i] = pk2(sm[((((2 * i) << 3) | hv) << 6) | tl],
                   sm[((((2 * i + 1) << 3) | hv) << 6) | tl]);

    // stage S global bits 19-21 (view B k bits 2-4)
    BF(p, 2, S, 19);
    BF(p, 3, S, 20);
    BF(p, 4, S, 21);

    // store from view B: h = (k<<3)|hv
#pragma unroll
    for (int i = 0; i < 16; i++) {
        float2 v = upk2(p[i]);
        g_state[((((2 * i) << 3) | hv) << LOWB) | low] = v.x;
        g_state[((((2 * i + 1) << 3) | hv) << LOWB) | low] = v.y;
    }
}

// ---------------------------------------------------------------- S3 passHE
// stage S hi RYs + fused expvals.
template <int S>
__global__ void __launch_bounds__(512, 2) k_passHE(float* __restrict__ out) {
    extern __shared__ float sm[];
    __shared__ float acc[NQ];
    const int t = threadIdx.x;
    const int lane = t & 31;
    const int tl = t & 63;
    const unsigned hv = t >> 6;
    const int low = (blockIdx.x << 6) + tl;

    if (t < NQ) acc[t] = 0.0f;

    ull p[16];
#pragma unroll
    for (int i = 0; i < 16; i++)
        p[i] = pk2(g_state[(((hv << 5) | (2 * i)) << LOWB) | low],
                   g_state[(((hv << 5) | (2 * i + 1)) << LOWB) | low]);

    BF(p, 0, S, 14);
    BF(p, 1, S, 15);
    BF(p, 2, S, 16);
    BF(p, 3, S, 17);
    BF(p, 4, S, 18);

#pragma unroll
    for (int i = 0; i < 16; i++) {
        float2 v = upk2(p[i]);
        sm[(((hv << 5) | (2 * i)) << 6) | tl] = v.x;
        sm[(((hv << 5) | (2 * i + 1)) << 6) | tl] = v.y;
    }
    __syncthreads();
#pragma unroll
    for (int i = 0; i < 16; i++)
        p[i] = pk2(sm[((((2 * i) << 3) | hv) << 6) | tl],
                   sm[((((2 * i + 1) << 3) | hv) << 6) | tl]);

    BF(p, 2, S, 19);
    BF(p, 3, S, 20);
    BF(p, 4, S, 21);

    // expvals, view B element bits: 0-5 = tl, 6-13 = blk, 14-16 = hv,
    // 17 = pair, 18-21 = i.
    float P = 0.f, S17 = 0.f, S18 = 0.f, S19 = 0.f, S20 = 0.f, S21 = 0.f;
#pragma unroll
    for (int i = 0; i < 16; i++) {
        float2 v = upk2(p[i]);
        float px = v.x * v.x, py = v.y * v.y;
        float pp = px + py;
        P += pp;
        S17 += px - py;
        S18 += (i & 1) ? -pp : pp;
        S19 += (i & 2) ? -pp : pp;
        S20 += (i & 4) ? -pp : pp;
        S21 += (i & 8) ? -pp : pp;
    }
    float R0 = (lane & 1)  ? -P : P;
    float R1 = (lane & 2)  ? -P : P;
    float R2 = (lane & 4)  ? -P : P;
    float R3 = (lane & 8)  ? -P : P;
    float R4 = (lane & 16) ? -P : P;
#pragma unroll
    for (int o = 16; o; o >>= 1) {
        P   += __shfl_xor_sync(FULL, P, o);
        S17 += __shfl_xor_sync(FULL, S17, o);
        S18 += __shfl_xor_sync(FULL, S18, o);
        S19 += __shfl_xor_sync(FULL, S19, o);
        S20 += __shfl_xor_sync(FULL, S20, o);
        S21 += __shfl_xor_sync(FULL, S21, o);
        R0  += __shfl_xor_sync(FULL, R0, o);
        R1  += __shfl_xor_sync(FULL, R1, o);
        R2  += __shfl_xor_sync(FULL, R2, o);
        R3  += __shfl_xor_sync(FULL, R3, o);
        R4  += __shfl_xor_sync(FULL, R4, o);
    }
    if (lane == 0) {
        unsigned w = (unsigned)(t >> 5);
        atomicAdd(&acc[0], R0);
        atomicAdd(&acc[1], R1);
        atomicAdd(&acc[2], R2);
        atomicAdd(&acc[3], R3);
        atomicAdd(&acc[4], R4);
        atomicAdd(&acc[5], (w & 1u) ? -P : P);
#pragma unroll
        for (int b = 6; b < 14; b++)
            atomicAdd(&acc[b], ((blockIdx.x >> (b - 6)) & 1) ? -P : P);
#pragma unroll
        for (int b = 14; b < 17; b++)
            atomicAdd(&acc[b], ((w >> (b - 13)) & 1u) ? -P : P);
        atomicAdd(&acc[17], S17);
        atomicAdd(&acc[18], S18);
        atomicAdd(&acc[19], S19);
        atomicAdd(&acc[20], S20);
        atomicAdd(&acc[21], S21);
    }
    __syncthreads();
    if (t < NQ) atomicAdd(&out[NQ - 1 - t], acc[t]);
}

// ---------------------------------------------------------------- L views
// Natural layout, pairs along x0. Swizzle keeps bit0: lw(x)=x^(((x>>5)&15)<<1).
__device__ __forceinline__ int lw(int x) { return x ^ (((x >> 5) & 15) << 1); }

// ---------------------------------------------------------------- S2 passLL
// SA = L2 bits 0-13 -> sign2 -> SB = L3 bits 0-13.
template <int SA, int SB>
__global__ void __launch_bounds__(512, 2) k_passLL() {
    extern __shared__ float sm[];   // 16384 floats
    const int t = threadIdx.x;           // 9 bits
    const int lane = t & 31;
    const int base = blockIdx.x << LOWB;
    const unsigned blk = blockIdx.x;
    ull p[16];

    // ---- load: natural ulonglong2, pairs along x0
    {
        const ulonglong2* gp =
            reinterpret_cast<const ulonglong2*>(&g_state[base + t * 32]);
#pragma unroll
        for (int j = 0; j < 8; j++) {
            ulonglong2 q = gp[j];
            p[2 * j] = q.x;
            p[2 * j + 1] = q.y;
        }
    }

    // ---- sign constants for the C view: x = blk<<14 | i<<10 | e<<9 | T9
    const int yc = ((t >> 4) & 1) | ((t & 15) << 1) | (((t >> 5) & 15) << 5);
    const unsigned T9 = (unsigned)yc;
    unsigned Mblk = 0;
#pragma unroll
    for (int j = 0; j < 8; j++)
        Mblk ^= (0u - ((blk >> j) & 1u)) & (c_pm[14 + j] & 0x3FFFu);
    unsigned Ablk = 0;
#pragma unroll
    for (int a = 1; a < 8; a++)
        Ablk ^= ((blk >> a) & 1u) & par(blk & ((c_pm[14 + a] >> 14) & ((1u << a) - 1u)));
    unsigned Bt = 0;
#pragma unroll
    for (int a = 1; a < 9; a++)
        Bt ^= ((T9 >> a) & 1u) & par(T9 & c_pm[a] & ((1u << a) - 1u));
    const unsigned base_t = Bt ^ par(T9 & Mblk & 0x1FFu) ^ Ablk;
    const unsigned X9c = par(T9 & c_pm[9] & 0x1FFu) ^ ((Mblk >> 9) & 1u);
    unsigned km = 0;
#pragma unroll
    for (int b = 0; b < 4; b++)
        km |= (par(T9 & c_pm[10 + b] & 0x1FFu) ^ ((Mblk >> (10 + b)) & 1u)) << b;
    const unsigned mask9i = (c_pm[9] >> 10) & 15u;
    unsigned ab = 0;
#pragma unroll
    for (int a = 1; a < 4; a++)
        ab ^= (((unsigned)lane >> a) & 1u) &
              par((unsigned)lane & ((c_pm[10 + a] >> 10) & ((1u << a) - 1u)));
    const unsigned Wakk = __ballot_sync(FULL, ab);

    // ---- A: SA bits 0-4 (x0 internal, x1-4 packed)
    BF(p, 0, SA, 0);
    BF(p, 1, SA, 1);
    BF(p, 2, SA, 2);
    BF(p, 3, SA, 3);
    BF(p, 4, SA, 4);

#pragma unroll
    for (int i = 0; i < 16; i++)
        *reinterpret_cast<ull*>(&sm[lw((t << 5) | (2 * i))]) = p[i];
    __syncthreads();

    // ---- B: SA bits 5-8
    const int yb = ((t & 15) << 1) | ((t >> 4) << 9);
#pragma unroll
    for (int i = 0; i < 16; i++)
        p[i] = *reinterpret_cast<const ull*>(&sm[lw(yb | (i << 5))]);

    BF(p, 1, SA, 5);
    BF(p, 2, SA, 6);
    BF(p, 3, SA, 7);
    BF(p, 4, SA, 8);

#pragma unroll
    for (int i = 0; i < 16; i++)
        *reinterpret_cast<ull*>(&sm[lw(yb | (i << 5))]) = p[i];
    __syncthreads();

    // ---- C: SA bits 9-13 -> SIGN -> SB bits 9-13
#pragma unroll
    for (int i = 0; i < 16; i++)
        p[i] = pk2(sm[lw(yc | ((2 * i) << 9))],
                   sm[lw(yc | ((2 * i + 1) << 9))]);

    BF(p, 0, SA, 9);
    BF(p, 1, SA, 10);
    BF(p, 2, SA, 11);
    BF(p, 3, SA, 12);
    BF(p, 4, SA, 13);

#pragma unroll
    for (int i = 0; i < 16; i++) {
        unsigned lo = base_t ^ par((unsigned)i & km) ^ ((Wakk >> i) & 1u);
        unsigned hi = lo ^ X9c ^ par((unsigned)i & mask9i);
        p[i] ^= ((ull)hi << 63) | ((ull)lo << 31);
    }

    BF(p, 0, SB, 9);
    BF(p, 1, SB, 10);
    BF(p, 2, SB, 11);
    BF(p, 3, SB, 12);
    BF(p, 4, SB, 13);

#pragma unroll
    for (int i = 0; i < 16; i++) {
        float2 v = upk2(p[i]);
        sm[lw(yc | ((2 * i) << 9))] = v.x;
        sm[lw(yc | ((2 * i + 1) << 9))] = v.y;
    }
    __syncthreads();

    // ---- B': SB bits 5-8
#pragma unroll
    for (int i = 0; i < 16; i++)
        p[i] = *reinterpret_cast<const ull*>(&sm[lw(yb | (i << 5))]);

    BF(p, 1, SB, 5);
    BF(p, 2, SB, 6);
    BF(p, 3, SB, 7);
    BF(p, 4, SB, 8);

#pragma unroll
    for (int i = 0; i < 16; i++)
        *reinterpret_cast<ull*>(&sm[lw(yb | (i << 5))]) = p[i];
    __syncthreads();

    // ---- A': SB bits 0-4, then natural ulonglong2 store
#pragma unroll
    for (int i = 0; i < 16; i++)
        p[i] = *reinterpret_cast<const ull*>(&sm[lw((t << 5) | (2 * i))]);

    BF(p, 0, SB, 0);
    BF(p, 1, SB, 1);
    BF(p, 2, SB, 2);
    BF(p, 3, SB, 3);
    BF(p, 4, SB, 4);

    {
        ulonglong2* gp = reinterpret_cast<ulonglong2*>(&g_state[base + t * 32]);
#pragma unroll
        for (int j = 0; j < 8; j++) {
            ulonglong2 q;
            q.x = p[2 * j];
            q.y = p[2 * j + 1];
            gp[j] = q;
        }
    }
}

// ---------------------------------------------------------------- launch
extern "C" void kernel_launch(void* const* d_in, const int* in_sizes, int n_in,
                              void* d_out, int out_size) {
    const float* feat = (const float*)d_in[0];
    const float* adj = (const float*)d_in[1];
    const float* params = (const float*)d_in[2];
    float* out = (float*)d_out;

    const int SMEM = LOWDIM * (int)sizeof(float);   // 65536
    cudaFuncSetAttribute(k_passIH<2>,    cudaFuncAttributeMaxDynamicSharedMemorySize, SMEM);
    cudaFuncSetAttribute(k_passLL<2, 3>, cudaFuncAttributeMaxDynamicSharedMemorySize, SMEM);
    cudaFuncSetAttribute(k_passHE<3>,    cudaFuncAttributeMaxDynamicSharedMemorySize, SMEM);

    k_setup<<<1, 128>>>(feat, adj, params, out);

    // stage coefficients into __constant__ (D2D, graph-capturable)
    void *pc = nullptr, *ps = nullptr, *pt = nullptr, *pm = nullptr;
    cudaGetSymbolAddress(&pc, g_ccs);
    cudaGetSymbolAddress(&ps, g_sss);
    cudaGetSymbolAddress(&pt, g_tts);
    cudaGetSymbolAddress(&pm, g_pms);
    cudaMemcpyToSymbolAsync(c_c, pc, sizeof(float) * 4 * NQ, 0, cudaMemcpyDeviceToDevice);
    cudaMemcpyToSymbolAsync(c_s, ps, sizeof(float) * 4 * NQ, 0, cudaMemcpyDeviceToDevice);
    cudaMemcpyToSymbolAsync(c_t, pt, sizeof(float) * 4 * NQ, 0, cudaMemcpyDeviceToDevice);
    cudaMemcpyToSymbolAsync(c_pm, pm, sizeof(unsigned) * NQ, 0, cudaMemcpyDeviceToDevice);

    k_passIH<2>   <<<LOWDIM / 64, 512, SMEM>>>();
    k_passLL<2, 3><<<DIM / LOWDIM, 512, SMEM>>>();
    k_passHE<3>   <<<LOWDIM / 64, 512, SMEM>>>(out);
}

// round 17
// speedup vs baseline: 1.1714x; 1.0484x over previous
#include <cuda_runtime.h>
#include <math.h>

// GraphQNN: 22-qubit real-amplitude state-vector simulation.
// R17: hybrid butterflies. R13 structure (3 sweeps, 512thr x 32elem).
//  - H kernels (passIH/passHE): LIFTING form (3 FMAs) - measured faster there
//    (memory-latency dominated; instruction cut wins; R16 passHE 11.6->11.0).
//  - passLL: DIRECT form (2 fma2 + 2 mul2, two independent chains) - the
//    lifting serial chain regressed this compute-dense kernel in R16.
//   S1 k_passIH: analytic init (combined L0+L1 angles) -> sign1 -> L2 hi
//   S2 k_passLL: L2 low -> sign2 -> L3 low
//   S3 k_passHE: L3 hi -> fused expvals

#define NQ 22
#define DIM (1 << NQ)
#define LOWB 14
#define LOWDIM (1 << LOWB)
#define FULL 0xffffffffu
typedef unsigned long long ull;

__device__ float g_state[DIM];
__device__ float g_ccs[4][NQ];     // staging, written by k_setup
__device__ float g_sss[4][NQ];
__device__ float g_tts[4][NQ];
__device__ unsigned g_pms[NQ];

__constant__ float c_c[4][NQ];     // cos(th/2)   [stage][bitpos]; stage0 = L0+L1
__constant__ float c_s[4][NQ];     // sin(th/2)
__constant__ float c_t[4][NQ];     // lifting coef s/(1+c)
__constant__ unsigned c_pm[NQ];

__device__ __forceinline__ unsigned par(unsigned v) {
    return (unsigned)__popc(v) & 1u;
}

// ---------------------------------------------------------------- f32x2
__device__ __forceinline__ ull pk2(float x, float y) {
    ull r; asm("mov.b64 %0, {%1,%2};" : "=l"(r) : "f"(x), "f"(y)); return r;
}
__device__ __forceinline__ float2 upk2(ull v) {
    float2 f; asm("mov.b64 {%0,%1}, %2;" : "=f"(f.x), "=f"(f.y) : "l"(v)); return f;
}
__device__ __forceinline__ ull mul2_(ull a, ull b) {
    ull r; asm("mul.rn.f32x2 %0, %1, %2;" : "=l"(r) : "l"(a), "l"(b)); return r;
}
__device__ __forceinline__ ull fma2_(ull a, ull b, ull c) {
    ull r; asm("fma.rn.f32x2 %0, %1, %2, %3;" : "=l"(r) : "l"(a), "l"(b), "l"(c)); return r;
}

// DIRECT butterfly (2 fma2 + 2 mul2, two independent chains) - for passLL.
template <int BIT>
__device__ __forceinline__ void bflyd(ull* p, float c, float s) {
    if (BIT == 0) {
#pragma unroll
        for (int i = 0; i < 16; i++) {
            float2 v = upk2(p[i]);
            p[i] = pk2(fmaf(c, v.x, -(s * v.y)), fmaf(s, v.x, c * v.y));
        }
    } else {
        const ull cc = pk2(c, c), ss = pk2(s, s), ns = pk2(-s, -s);
#pragma unroll
        for (int i0 = 0; i0 < 16; i0++) {
            if ((i0 & (1 << (BIT - 1))) == 0) {
                int i1 = i0 | (1 << (BIT - 1));
                ull v0 = p[i0], v1 = p[i1];
                p[i0] = fma2_(cc, v0, mul2_(ns, v1));
                p[i1] = fma2_(ss, v0, mul2_(cc, v1));
            }
        }
    }
}

// LIFTING butterfly (3 FMAs, serial) - for H kernels.
// (x,y) -> (c x - s y, s x + c y) via x-=t*y; y+=s*x; x-=t*y.
template <int BIT>
__device__ __forceinline__ void bflyl(ull* p, float s, float t) {
    if (BIT == 0) {
        const float nt = -t;
#pragma unroll
        for (int i = 0; i < 16; i++) {
            float2 v = upk2(p[i]);
            v.x = fmaf(nt, v.y, v.x);
            v.y = fmaf(s, v.x, v.y);
            v.x = fmaf(nt, v.y, v.x);
            p[i] = pk2(v.x, v.y);
        }
    } else {
        const ull nt = pk2(-t, -t), ss = pk2(s, s);
#pragma unroll
        for (int i0 = 0; i0 < 16; i0++) {
            if ((i0 & (1 << (BIT - 1))) == 0) {
                int i1 = i0 | (1 << (BIT - 1));
                ull v0 = p[i0], v1 = p[i1];
                v0 = fma2_(nt, v1, v0);
                v1 = fma2_(ss, v0, v1);
                v0 = fma2_(nt, v1, v0);
                p[i0] = v0;
                p[i1] = v1;
            }
        }
    }
}

#define BFL(P, BIT, S, b) bflyl<BIT>(P, c_s[S][b], c_t[S][b])
#define BFD(P, BIT, S, b) bflyd<BIT>(P, c_c[S][b], c_s[S][b])

// ---------------------------------------------------------------- setup
__global__ void k_setup(const float* __restrict__ feat,
                        const float* __restrict__ adj,
                        const float* __restrict__ params,
                        float* __restrict__ out) {
    int t = threadIdx.x;
    if (t < 4 * NQ) {
        int s = t / NQ;
        int b = t % NQ;
        int q = NQ - 1 - b;
        float th;
        if (s == 0)       th = (feat[q] + params[q]) * 0.5f;   // combined L0+L1
        else              th = params[(s - 1) * NQ + q] * 0.5f;
        float c = cosf(th), sn = sinf(th);
        g_ccs[s][b] = c;
        g_sss[s][b] = sn;
        g_tts[s][b] = sn / (1.0f + c);
    }
    if (t < NQ) {
        int q = NQ - 1 - t;
        unsigned m = 0;
        for (int qq = 0; qq < NQ; qq++) {
            if (qq == q) continue;
            int i = q < qq ? q : qq;
            int j = q < qq ? qq : q;
            if (adj[i * NQ + j] > 0.0f) m |= (1u << (NQ - 1 - qq));
        }
        g_pms[t] = m;
        out[t] = 0.0f;
    }
}

__device__ __forceinline__ unsigned signB(unsigned ulow) {
    unsigned Bb = 0;
#pragma unroll
    for (int a = 1; a < LOWB; a++)
        Bb ^= ((ulow >> a) & 1u) & par(ulow & c_pm[a] & ((1u << a) - 1u));
    return Bb;
}
__device__ __forceinline__ unsigned signCL(unsigned ulow) {
    unsigned cl = 0;
#pragma unroll
    for (int j = 0; j < 8; j++)
        cl |= par(ulow & c_pm[14 + j] & 0x3FFFu) << j;
    return cl;
}

// ---------------------------------------------------------------- S1 passIH
// Analytic post-L1 product state -> sign1 -> stage S hi RYs -> store.
template <int S>
__global__ void __launch_bounds__(512, 2) k_passIH() {
    extern __shared__ float sm[];
    const int t = threadIdx.x;
    const int lane = t & 31;
    const int tl = t & 63;
    const unsigned hv = t >> 6;          // global 19-21
    const int low = (blockIdx.x << 6) + tl;
    const unsigned ulow = (unsigned)low;

    // ---- sign constants (VIEW A)
    unsigned Bb = signB(ulow);
    unsigned cl = signCL(ulow);
    unsigned chm = 0;
#pragma unroll
    for (int a = 0; a < 5; a++)
        chm |= par(hv & ((c_pm[14 + a] >> 19) & 7u)) << a;
    unsigned Ahh = 0;
#pragma unroll
    for (int a = 1; a < 3; a++)
        Ahh ^= ((hv >> a) & 1u) & par(hv & ((c_pm[19 + a] >> 19) & ((1u << a) - 1u)));
    unsigned ab = 0;
#pragma unroll
    for (int a = 1; a < 5; a++)
        ab ^= (((unsigned)lane >> a) & 1u) &
              par((unsigned)lane & ((c_pm[14 + a] >> 14) & ((1u << a) - 1u)));
    const unsigned akk = __ballot_sync(FULL, ab);
    const unsigned km = (cl & 31u) ^ chm;
    const unsigned cbase = Bb ^ par(hv & (cl >> 5)) ^ Ahh;

    // ---- analytic product state (combined angles, stage 0)
    float a = 1.0f;
#pragma unroll
    for (int b = 0; b < LOWB; b++)
        a *= ((ulow >> b) & 1u) ? c_s[0][b] : c_c[0][b];
#pragma unroll
    for (int b = 0; b < 3; b++)
        a *= ((hv >> b) & 1u) ? c_s[0][19 + b] : c_c[0][19 + b];

    ull p[16];
#pragma unroll
    for (int i = 0; i < 16; i++) {
        float ai = a;
#pragma unroll
        for (int b = 0; b < 4; b++)               // k bits 1-4 = global 15-18
            ai *= ((i >> b) & 1) ? c_s[0][15 + b] : c_c[0][15 + b];
        float vlo = ai * c_c[0][14];              // k bit 0 (global 14) = 0
        float vhi = ai * c_s[0][14];              // k bit 0 = 1
        unsigned lo = cbase ^ ((akk >> (2 * i)) & 1u) ^ par((unsigned)(2 * i) & km);
        unsigned hi = cbase ^ ((akk >> (2 * i + 1)) & 1u) ^ par((unsigned)(2 * i + 1) & km);
        p[i] = pk2(__int_as_float(__float_as_int(vlo) ^ (lo << 31)),
                   __int_as_float(__float_as_int(vhi) ^ (hi << 31)));
    }

    // stage S global bits 14-18 (lifting)
    BFL(p, 0, S, 14);
    BFL(p, 1, S, 15);
    BFL(p, 2, S, 16);
    BFL(p, 3, S, 17);
    BFL(p, 4, S, 18);

    // exchange A -> B (scalar, [h][tl], conflict-free)
#pragma unroll
    for (int i = 0; i < 16; i++) {
        float2 v = upk2(p[i]);
        sm[(((hv << 5) | (2 * i)) << 6) | tl] = v.x;
        sm[(((hv << 5) | (2 * i + 1)) << 6) | tl] = v.y;
    }
    __syncthreads();
#pragma unroll
    for (int i = 0; i < 16; i++)
        p[i] = pk2(sm[((((2 * i) << 3) | hv) << 6) | tl],
                   sm[((((2 * i + 1) << 3) | hv) << 6) | tl]);

    // stage S global bits 19-21 (view B k bits 2-4)
    BFL(p, 2, S, 19);
    BFL(p, 3, S, 20);
    BFL(p, 4, S, 21);

    // store from view B: h = (k<<3)|hv
#pragma unroll
    for (int i = 0; i < 16; i++) {
        float2 v = upk2(p[i]);
        g_state[((((2 * i) << 3) | hv) << LOWB) | low] = v.x;
        g_state[((((2 * i + 1) << 3) | hv) << LOWB) | low] = v.y;
    }
}

// ---------------------------------------------------------------- S3 passHE
// stage S hi RYs + fused expvals (lifting butterflies).
template <int S>
__global__ void __launch_bounds__(512, 2) k_passHE(float* __restrict__ out) {
    extern __shared__ float sm[];
    __shared__ float acc[NQ];
    const int t = threadIdx.x;
    const int lane = t & 31;
    const int tl = t & 63;
    const unsigned hv = t >> 6;
    const int low = (blockIdx.x << 6) + tl;

    if (t < NQ) acc[t] = 0.0f;

    ull p[16];
#pragma unroll
    for (int i = 0; i < 16; i++)
        p[i] = pk2(g_state[(((hv << 5) | (2 * i)) << LOWB) | low],
                   g_state[(((hv << 5) | (2 * i + 1)) << LOWB) | low]);

    BFL(p, 0, S, 14);
    BFL(p, 1, S, 15);
    BFL(p, 2, S, 16);
    BFL(p, 3, S, 17);
    BFL(p, 4, S, 18);

#pragma unroll
    for (int i = 0; i < 16; i++) {
        float2 v = upk2(p[i]);
        sm[(((hv << 5) | (2 * i)) << 6) | tl] = v.x;
        sm[(((hv << 5) | (2 * i + 1)) << 6) | tl] = v.y;
    }
    __syncthreads();
#pragma unroll
    for (int i = 0; i < 16; i++)
        p[i] = pk2(sm[((((2 * i) << 3) | hv) << 6) | tl],
                   sm[((((2 * i + 1) << 3) | hv) << 6) | tl]);

    BFL(p, 2, S, 19);
    BFL(p, 3, S, 20);
    BFL(p, 4, S, 21);

    // expvals, view B element bits: 0-5 = tl, 6-13 = blk, 14-16 = hv,
    // 17 = pair, 18-21 = i.
    float P = 0.f, S17 = 0.f, S18 = 0.f, S19 = 0.f, S20 = 0.f, S21 = 0.f;
#pragma unroll
    for (int i = 0; i < 16; i++) {
        float2 v = upk2(p[i]);
        float px = v.x * v.x, py = v.y * v.y;
        float pp = px + py;
        P += pp;
        S17 += px - py;
        S18 += (i & 1) ? -pp : pp;
        S19 += (i & 2) ? -pp : pp;
        S20 += (i & 4) ? -pp : pp;
        S21 += (i & 8) ? -pp : pp;
    }
    float R0 = (lane & 1)  ? -P : P;
    float R1 = (lane & 2)  ? -P : P;
    float R2 = (lane & 4)  ? -P : P;
    float R3 = (lane & 8)  ? -P : P;
    float R4 = (lane & 16) ? -P : P;
#pragma unroll
    for (int o = 16; o; o >>= 1) {
        P   += __shfl_xor_sync(FULL, P, o);
        S17 += __shfl_xor_sync(FULL, S17, o);
        S18 += __shfl_xor_sync(FULL, S18, o);
        S19 += __shfl_xor_sync(FULL, S19, o);
        S20 += __shfl_xor_sync(FULL, S20, o);
        S21 += __shfl_xor_sync(FULL, S21, o);
        R0  += __shfl_xor_sync(FULL, R0, o);
        R1  += __shfl_xor_sync(FULL, R1, o);
        R2  += __shfl_xor_sync(FULL, R2, o);
        R3  += __shfl_xor_sync(FULL, R3, o);
        R4  += __shfl_xor_sync(FULL, R4, o);
    }
    if (lane == 0) {
        unsigned w = (unsigned)(t >> 5);
        atomicAdd(&acc[0], R0);
        atomicAdd(&acc[1], R1);
        atomicAdd(&acc[2], R2);
        atomicAdd(&acc[3], R3);
        atomicAdd(&acc[4], R4);
        atomicAdd(&acc[5], (w & 1u) ? -P : P);
#pragma unroll
        for (int b = 6; b < 14; b++)
            atomicAdd(&acc[b], ((blockIdx.x >> (b - 6)) & 1) ? -P : P);
#pragma unroll
        for (int b = 14; b < 17; b++)
            atomicAdd(&acc[b], ((w >> (b - 13)) & 1u) ? -P : P);
        atomicAdd(&acc[17], S17);
        atomicAdd(&acc[18], S18);
        atomicAdd(&acc[19], S19);
        atomicAdd(&acc[20], S20);
        atomicAdd(&acc[21], S21);
    }
    __syncthreads();
    if (t < NQ) atomicAdd(&out[NQ - 1 - t], acc[t]);
}

// ---------------------------------------------------------------- L views
// Natural layout, pairs along x0. Swizzle keeps bit0: lw(x)=x^(((x>>5)&15)<<1).
__device__ __forceinline__ int lw(int x) { return x ^ (((x >> 5) & 15) << 1); }

// ---------------------------------------------------------------- S2 passLL
// SA = L2 bits 0-13 -> sign2 -> SB = L3 bits 0-13 (direct butterflies).
template <int SA, int SB>
__global__ void __launch_bounds__(512, 2) k_passLL() {
    extern __shared__ float sm[];   // 16384 floats
    const int t = threadIdx.x;           // 9 bits
    const int lane = t & 31;
    const int base = blockIdx.x << LOWB;
    const unsigned blk = blockIdx.x;
    ull p[16];

    // ---- load: natural ulonglong2, pairs along x0
    {
        const ulonglong2* gp =
            reinterpret_cast<const ulonglong2*>(&g_state[base + t * 32]);
#pragma unroll
        for (int j = 0; j < 8; j++) {
            ulonglong2 q = gp[j];
            p[2 * j] = q.x;
            p[2 * j + 1] = q.y;
        }
    }

    // ---- sign constants for the C view: x = blk<<14 | i<<10 | e<<9 | T9
    const int yc = ((t >> 4) & 1) | ((t & 15) << 1) | (((t >> 5) & 15) << 5);
    const unsigned T9 = (unsigned)yc;
    unsigned Mblk = 0;
#pragma unroll
    for (int j = 0; j < 8; j++)
        Mblk ^= (0u - ((blk >> j) & 1u)) & (c_pm[14 + j] & 0x3FFFu);
    unsigned Ablk = 0;
#pragma unroll
    for (int a = 1; a < 8; a++)
        Ablk ^= ((blk >> a) & 1u) & par(blk & ((c_pm[14 + a] >> 14) & ((1u << a) - 1u)));
    unsigned Bt = 0;
#pragma unroll
    for (int a = 1; a < 9; a++)
        Bt ^= ((T9 >> a) & 1u) & par(T9 & c_pm[a] & ((1u << a) - 1u));
    const unsigned base_t = Bt ^ par(T9 & Mblk & 0x1FFu) ^ Ablk;
    const unsigned X9c = par(T9 & c_pm[9] & 0x1FFu) ^ ((Mblk >> 9) & 1u);
    unsigned km = 0;
#pragma unroll
    for (int b = 0; b < 4; b++)
        km |= (par(T9 & c_pm[10 + b] & 0x1FFu) ^ ((Mblk >> (10 + b)) & 1u)) << b;
    const unsigned mask9i = (c_pm[9] >> 10) & 15u;
    unsigned ab = 0;
#pragma unroll
    for (int a = 1; a < 4; a++)
        ab ^= (((unsigned)lane >> a) & 1u) &
              par((unsigned)lane & ((c_pm[10 + a] >> 10) & ((1u << a) - 1u)));
    const unsigned Wakk = __ballot_sync(FULL, ab);

    // ---- A: SA bits 0-4 (x0 internal, x1-4 packed)
    BFD(p, 0, SA, 0);
    BFD(p, 1, SA, 1);
    BFD(p, 2, SA, 2);
    BFD(p, 3, SA, 3);
    BFD(p, 4, SA, 4);

#pragma unroll
    for (int i = 0; i < 16; i++)
        *reinterpret_cast<ull*>(&sm[lw((t << 5) | (2 * i))]) = p[i];
    __syncthreads();

    // ---- B: SA bits 5-8
    const int yb = ((t & 15) << 1) | ((t >> 4) << 9);
#pragma unroll
    for (int i = 0; i < 16; i++)
        p[i] = *reinterpret_cast<const ull*>(&sm[lw(yb | (i << 5))]);

    BFD(p, 1, SA, 5);
    BFD(p, 2, SA, 6);
    BFD(p, 3, SA, 7);
    BFD(p, 4, SA, 8);

#pragma unroll
    for (int i = 0; i < 16; i++)
        *reinterpret_cast<ull*>(&sm[lw(yb | (i << 5))]) = p[i];
    __syncthreads();

    // ---- C: SA bits 9-13 -> SIGN -> SB bits 9-13
#pragma unroll
    for (int i = 0; i < 16; i++)
        p[i] = pk2(sm[lw(yc | ((2 * i) << 9))],
                   sm[lw(yc | ((2 * i + 1) << 9))]);

    BFD(p, 0, SA, 9);
    BFD(p, 1, SA, 10);
    BFD(p, 2, SA, 11);
    BFD(p, 3, SA, 12);
    BFD(p, 4, SA, 13);

#pragma unroll
    for (int i = 0; i < 16; i++) {
        unsigned lo = base_t ^ par((unsigned)i & km) ^ ((Wakk >> i) & 1u);
        unsigned hi = lo ^ X9c ^ par((unsigned)i & mask9i);
        p[i] ^= ((ull)hi << 63) | ((ull)lo << 31);
    }

    BFD(p, 0, SB, 9);
    BFD(p, 1, SB, 10);
    BFD(p, 2, SB, 11);
    BFD(p, 3, SB, 12);
    BFD(p, 4, SB, 13);

#pragma unroll
    for (int i = 0; i < 16; i++) {
        float2 v = upk2(p[i]);
        sm[lw(yc | ((2 * i) << 9))] = v.x;
        sm[lw(yc | ((2 * i + 1) << 9))] = v.y;
    }
    __syncthreads();

    // ---- B': SB bits 5-8
#pragma unroll
    for (int i = 0; i < 16; i++)
        p[i] = *reinterpret_cast<const ull*>(&sm[lw(yb | (i << 5))]);

    BFD(p, 1, SB, 5);
    BFD(p, 2, SB, 6);
    BFD(p, 3, SB, 7);
    BFD(p, 4, SB, 8);

#pragma unroll
    for (int i = 0; i < 16; i++)
        *reinterpret_cast<ull*>(&sm[lw(yb | (i << 5))]) = p[i];
    __syncthreads();

    // ---- A': SB bits 0-4, then natural ulonglong2 store
#pragma unroll
    for (int i = 0; i < 16; i++)
        p[i] = *reinterpret_cast<const ull*>(&sm[lw((t << 5) | (2 * i))]);

    BFD(p, 0, SB, 0);
    BFD(p, 1, SB, 1);
    BFD(p, 2, SB, 2);
    BFD(p, 3, SB, 3);
    BFD(p, 4, SB, 4);

    {
        ulonglong2* gp = reinterpret_cast<ulonglong2*>(&g_state[base + t * 32]);
#pragma unroll
        for (int j = 0; j < 8; j++) {
            ulonglong2 q;
            q.x = p[2 * j];
            q.y = p[2 * j + 1];
            gp[j] = q;
        }
    }
}

// ---------------------------------------------------------------- launch
extern "C" void kernel_launch(void* const* d_in, const int* in_sizes, int n_in,
                              void* d_out, int out_size) {
    const float* feat = (const float*)d_in[0];
    const float* adj = (const float*)d_in[1];
    const float* params = (const float*)d_in[2];
    float* out = (float*)d_out;

    const int SMEM = LOWDIM * (int)sizeof(float);   // 65536
    cudaFuncSetAttribute(k_passIH<2>,    cudaFuncAttributeMaxDynamicSharedMemorySize, SMEM);
    cudaFuncSetAttribute(k_passLL<2, 3>, cudaFuncAttributeMaxDynamicSharedMemorySize, SMEM);
    cudaFuncSetAttribute(k_passHE<3>,    cudaFuncAttributeMaxDynamicSharedMemorySize, SMEM);

    k_setup<<<1, 128>>>(feat, adj, params, out);

    // stage coefficients into __constant__ (D2D, graph-capturable)
    void *pc = nullptr, *ps = nullptr, *pt = nullptr, *pm = nullptr;
    cudaGetSymbolAddress(&pc, g_ccs);
    cudaGetSymbolAddress(&ps, g_sss);
    cudaGetSymbolAddress(&pt, g_tts);
    cudaGetSymbolAddress(&pm, g_pms);
    cudaMemcpyToSymbolAsync(c_c, pc, sizeof(float) * 4 * NQ, 0, cudaMemcpyDeviceToDevice);
    cudaMemcpyToSymbolAsync(c_s, ps, sizeof(float) * 4 * NQ, 0, cudaMemcpyDeviceToDevice);
    cudaMemcpyToSymbolAsync(c_t, pt, sizeof(float) * 4 * NQ, 0, cudaMemcpyDeviceToDevice);
    cudaMemcpyToSymbolAsync(c_pm, pm, sizeof(unsigned) * NQ, 0, cudaMemcpyDeviceToDevice);

    k_passIH<2>   <<<LOWDIM / 64, 512, SMEM>>>();
    k_passLL<2, 3><<<DIM / LOWDIM, 512, SMEM>>>();
    k_passHE<3>   <<<LOWDIM / 64, 512, SMEM>>>(out);
}